// round 3
// baseline (speedup 1.0000x reference)
#include <cuda_runtime.h>
#include <cuda_bf16.h>
#include <math.h>

// ---------------------------------------------------------------------------
// Problem constants
// ---------------------------------------------------------------------------
#define Vc 32000
#define Ec 1024
#define Tc 2048
#define Hc 16
#define Dhc 64
#define Lc 4
#define FFc 4096
#define Bc 4
#define BTc (Bc * Tc)          // 8192 rows
#define ROWSQKV (Bc * Tc * Hc) // 131072 rows of 64

// ---------------------------------------------------------------------------
// Scratch (device globals; no allocation allowed)
// ---------------------------------------------------------------------------
__device__ float g_x[BTc * Ec];     // activations [B,T,E]
__device__ float g_q[BTc * Ec];
__device__ float g_k[BTc * Ec];
__device__ float g_v[BTc * Ec];
__device__ float g_att[BTc * Ec];   // attention output [B,T,E]
__device__ float g_tmp[BTc * Ec];   // pre-LN residual sums
__device__ float g_h[BTc * FFc];    // FFN hidden
__device__ float g_rl[BTc];         // per-row loss

// ---------------------------------------------------------------------------
// Embedding: x[b,t,:] = tok_emb[idx[b,t],:] + pos_emb[t,:]
// ---------------------------------------------------------------------------
__global__ void embed_kernel(const int* __restrict__ idx,
                             const float* __restrict__ tok,
                             const float* __restrict__ pos,
                             float* __restrict__ x) {
    int bt = blockIdx.x;
    int tid = threadIdx.x;
    int token = idx[bt];
    int t = bt % Tc;
    float4 a = *(const float4*)(tok + (size_t)token * Ec + tid * 4);
    float4 p = *(const float4*)(pos + (size_t)t * Ec + tid * 4);
    float4 r;
    r.x = a.x + p.x; r.y = a.y + p.y; r.z = a.z + p.z; r.w = a.w + p.w;
    *(float4*)(x + (size_t)bt * Ec + tid * 4) = r;
}

// ---------------------------------------------------------------------------
// Generic SGEMM: C[m,n] = sum_k A[m,k]*W[n,k] + bias[n]  (y = x @ W^T + b)
// Optional exact GELU, optional residual add (resid same shape as C).
// BM=BN=128, BK=8, TM=TN=8, 256 threads. Requires M%128==0, K%8==0.
// N may be arbitrary (guarded).
// ---------------------------------------------------------------------------
__global__ __launch_bounds__(256)
void gemm_kernel(const float* __restrict__ A, const float* __restrict__ W,
                 const float* __restrict__ bias, const float* __restrict__ resid,
                 float* __restrict__ C, int M, int N, int K, int do_gelu) {
    __shared__ float As[8][128];
    __shared__ float Ws[8][128];

    int tid = threadIdx.x;
    int tx = tid % 16;       // n sub-tile
    int ty = tid / 16;       // m sub-tile
    int m0 = blockIdx.y * 128;
    int n0 = blockIdx.x * 128;

    float acc[8][8];
#pragma unroll
    for (int i = 0; i < 8; i++)
#pragma unroll
        for (int j = 0; j < 8; j++) acc[i][j] = 0.f;

    int arow = tid >> 1;            // 0..127
    int acol = (tid & 1) * 4;       // 0 or 4
    const float* Aptr = A + (size_t)(m0 + arow) * K + acol;
    bool wvalid = (n0 + arow) < N;
    const float* Wptr = W + (size_t)(n0 + arow) * K + acol;

    for (int k0 = 0; k0 < K; k0 += 8) {
        float4 av = *(const float4*)(Aptr + k0);
        float4 wv = wvalid ? *(const float4*)(Wptr + k0) : make_float4(0.f, 0.f, 0.f, 0.f);
        As[acol + 0][arow] = av.x;
        As[acol + 1][arow] = av.y;
        As[acol + 2][arow] = av.z;
        As[acol + 3][arow] = av.w;
        Ws[acol + 0][arow] = wv.x;
        Ws[acol + 1][arow] = wv.y;
        Ws[acol + 2][arow] = wv.z;
        Ws[acol + 3][arow] = wv.w;
        __syncthreads();

#pragma unroll
        for (int k = 0; k < 8; k++) {
            float4 a0 = *(const float4*)&As[k][ty * 8];
            float4 a1 = *(const float4*)&As[k][ty * 8 + 4];
            float4 b0 = *(const float4*)&Ws[k][tx * 8];
            float4 b1 = *(const float4*)&Ws[k][tx * 8 + 4];
            float ar[8] = {a0.x, a0.y, a0.z, a0.w, a1.x, a1.y, a1.z, a1.w};
            float br[8] = {b0.x, b0.y, b0.z, b0.w, b1.x, b1.y, b1.z, b1.w};
#pragma unroll
            for (int i = 0; i < 8; i++)
#pragma unroll
                for (int j = 0; j < 8; j++) acc[i][j] += ar[i] * br[j];
        }
        __syncthreads();
    }

#pragma unroll
    for (int i = 0; i < 8; i++) {
        int mrow = m0 + ty * 8 + i;
#pragma unroll
        for (int j = 0; j < 8; j++) {
            int ncol = n0 + tx * 8 + j;
            if (ncol < N) {
                float v = acc[i][j];
                if (bias) v += bias[ncol];
                if (do_gelu) v = 0.5f * v * (1.f + erff(v * 0.70710678118654752f));
                if (resid) v += resid[(size_t)mrow * N + ncol];
                C[(size_t)mrow * N + ncol] = v;
            }
        }
    }
}

// ---------------------------------------------------------------------------
// LayerNorm over last dim (E=1024). One block (256 thr) per row.
// ---------------------------------------------------------------------------
__global__ __launch_bounds__(256)
void layernorm_kernel(const float* __restrict__ in, const float* __restrict__ gamma,
                      const float* __restrict__ beta, float* __restrict__ out) {
    __shared__ float red[256];
    int row = blockIdx.x;
    int tid = threadIdx.x;
    const float* x = in + (size_t)row * Ec;
    float4 xv = *(const float4*)(x + tid * 4);

    float s = xv.x + xv.y + xv.z + xv.w;
    red[tid] = s;
    __syncthreads();
#pragma unroll
    for (int st = 128; st; st >>= 1) {
        if (tid < st) red[tid] += red[tid + st];
        __syncthreads();
    }
    float mean = red[0] * (1.f / Ec);
    __syncthreads();

    float d0 = xv.x - mean, d1 = xv.y - mean, d2 = xv.z - mean, d3 = xv.w - mean;
    red[tid] = d0 * d0 + d1 * d1 + d2 * d2 + d3 * d3;
    __syncthreads();
#pragma unroll
    for (int st = 128; st; st >>= 1) {
        if (tid < st) red[tid] += red[tid + st];
        __syncthreads();
    }
    float var = red[0] * (1.f / Ec);
    float r = rsqrtf(var + 1e-5f);

    float4 gv = *(const float4*)(gamma + tid * 4);
    float4 bv = *(const float4*)(beta + tid * 4);
    float4 o;
    o.x = d0 * r * gv.x + bv.x;
    o.y = d1 * r * gv.y + bv.y;
    o.z = d2 * r * gv.z + bv.z;
    o.w = d3 * r * gv.w + bv.w;
    *(float4*)(out + (size_t)row * Ec + tid * 4) = o;
}

// ---------------------------------------------------------------------------
// Causal flash attention. Layout of Q/K/V/O: [B,T,H,Dh] (contiguous = [B,T,E]).
// Block = 256 threads = 8 warps; warp w owns query q = blockIdx.x*8 + w.
// Key tiles of 64 staged in smem (padded rows to kill bank conflicts).
// Online softmax; scale = 1/sqrt(64) = 0.125.
// ---------------------------------------------------------------------------
__global__ __launch_bounds__(256)
void attn_kernel(const float* __restrict__ Q, const float* __restrict__ Kb,
                 const float* __restrict__ Vb, float* __restrict__ O) {
    __shared__ float Ks[64][65];
    __shared__ float Vs[64][65];
    __shared__ float qs[8][65];
    __shared__ float ps[8][64];

    int tid = threadIdx.x;
    int w = tid >> 5;
    int lane = tid & 31;
    int qblk = blockIdx.x;        // 0..T/8-1
    int bh = blockIdx.y;          // b*H + h
    int b = bh / Hc, h = bh % Hc;
    int q = qblk * 8 + w;

    // stage the 8 query rows
    for (int i = tid; i < 8 * 64; i += 256) {
        int qq = i >> 6, d = i & 63;
        qs[qq][d] = Q[(((size_t)b * Tc + qblk * 8 + qq) * Hc + h) * Dhc + d];
    }
    __syncthreads();

    float m = -INFINITY, l = 0.f, o0 = 0.f, o1 = 0.f;
    int d0 = lane, d1 = lane + 32;
    int j0 = lane, j1 = lane + 32;
    int kmax = qblk * 8 + 7;
    int ntiles = (kmax + 64) / 64;

    for (int t = 0; t < ntiles; t++) {
        int k0 = t * 64;
        for (int i = tid; i < 64 * 64; i += 256) {
            int r = i >> 6, c = i & 63;
            size_t gidx = (((size_t)b * Tc + k0 + r) * Hc + h) * Dhc + c;
            Ks[r][c] = Kb[gidx];
            Vs[r][c] = Vb[gidx];
        }
        __syncthreads();

        float s0 = 0.f, s1 = 0.f;
#pragma unroll 16
        for (int d = 0; d < 64; d++) {
            float qd = qs[w][d];
            s0 += qd * Ks[j0][d];
            s1 += qd * Ks[j1][d];
        }
        s0 *= 0.125f;
        s1 *= 0.125f;
        if (k0 + j0 > q) s0 = -INFINITY;
        if (k0 + j1 > q) s1 = -INFINITY;

        float smax = fmaxf(s0, s1);
#pragma unroll
        for (int off = 16; off; off >>= 1)
            smax = fmaxf(smax, __shfl_xor_sync(0xFFFFFFFFu, smax, off));
        float mnew = fmaxf(m, smax);
        float alpha = expf(m - mnew);       // 0 on first tile (m = -inf)
        float p0 = expf(s0 - mnew);
        float p1 = expf(s1 - mnew);
        float psum = p0 + p1;
#pragma unroll
        for (int off = 16; off; off >>= 1)
            psum += __shfl_xor_sync(0xFFFFFFFFu, psum, off);
        l = l * alpha + psum;
        o0 *= alpha;
        o1 *= alpha;
        ps[w][j0] = p0;
        ps[w][j1] = p1;
        __syncwarp();
#pragma unroll 16
        for (int j = 0; j < 64; j++) {
            float pj = ps[w][j];
            o0 += pj * Vs[j][d0];
            o1 += pj * Vs[j][d1];
        }
        m = mnew;
        __syncthreads();
    }

    float inv = 1.f / l;
    size_t ob = (((size_t)b * Tc + q) * Hc + h) * Dhc;
    O[ob + d0] = o0 * inv;
    O[ob + d1] = o1 * inv;
}

// ---------------------------------------------------------------------------
// Per-row loss: rl[r] = logsumexp(logits[r,:]) - logits[r, target[r]]
// ---------------------------------------------------------------------------
__global__ __launch_bounds__(256)
void rowloss_kernel(const float* __restrict__ logits, const int* __restrict__ targets,
                    float* __restrict__ rl) {
    __shared__ float red[256];
    int row = blockIdx.x;
    int tid = threadIdx.x;
    const float* lg = logits + (size_t)row * Vc;

    float mx = -INFINITY;
    for (int i = tid; i < Vc; i += 256) mx = fmaxf(mx, lg[i]);
    red[tid] = mx;
    __syncthreads();
#pragma unroll
    for (int st = 128; st; st >>= 1) {
        if (tid < st) red[tid] = fmaxf(red[tid], red[tid + st]);
        __syncthreads();
    }
    mx = red[0];
    __syncthreads();

    float s = 0.f;
    for (int i = tid; i < Vc; i += 256) s += expf(lg[i] - mx);
    red[tid] = s;
    __syncthreads();
#pragma unroll
    for (int st = 128; st; st >>= 1) {
        if (tid < st) red[tid] += red[tid + st];
        __syncthreads();
    }
    if (tid == 0) rl[row] = (mx + logf(red[0])) - lg[targets[row]];
}

__global__ __launch_bounds__(256)
void loss_reduce_kernel(const float* __restrict__ rl, float* __restrict__ out) {
    __shared__ float red[256];
    int tid = threadIdx.x;
    float s = 0.f;
    for (int i = tid; i < BTc; i += 256) s += rl[i];
    red[tid] = s;
    __syncthreads();
#pragma unroll
    for (int st = 128; st; st >>= 1) {
        if (tid < st) red[tid] += red[tid + st];
        __syncthreads();
    }
    if (tid == 0) *out = red[0] / (float)BTc;
}

// ---------------------------------------------------------------------------
// Host orchestration (graph-capturable: kernel launches only)
// ---------------------------------------------------------------------------
extern "C" void kernel_launch(void* const* d_in, const int* in_sizes, int n_in,
                              void* d_out, int out_size) {
    const int*   idx     = (const int*)d_in[0];
    const int*   targets = (const int*)d_in[1];
    const float* tok_emb = (const float*)d_in[2];
    const float* pos_emb = (const float*)d_in[3];
    const float* Wq      = (const float*)d_in[4];
    const float* Wk      = (const float*)d_in[5];
    const float* Wv      = (const float*)d_in[6];
    const float* Wo      = (const float*)d_in[7];
    const float* bo      = (const float*)d_in[8];
    const float* ln1_g   = (const float*)d_in[9];
    const float* ln1_b   = (const float*)d_in[10];
    const float* W1      = (const float*)d_in[11];
    const float* b1      = (const float*)d_in[12];
    const float* W2      = (const float*)d_in[13];
    const float* b2      = (const float*)d_in[14];
    const float* ln2_g   = (const float*)d_in[15];
    const float* ln2_b   = (const float*)d_in[16];
    const float* lnf_g   = (const float*)d_in[17];
    const float* lnf_b   = (const float*)d_in[18];
    const float* lm_w    = (const float*)d_in[19];
    const float* lm_b    = (const float*)d_in[20];

    static float *px = nullptr, *pq, *pk, *pv, *patt, *ptmp, *ph, *prl;
    if (!px) {
        void* p;
        cudaGetSymbolAddress(&p, g_x);   px   = (float*)p;
        cudaGetSymbolAddress(&p, g_q);   pq   = (float*)p;
        cudaGetSymbolAddress(&p, g_k);   pk   = (float*)p;
        cudaGetSymbolAddress(&p, g_v);   pv   = (float*)p;
        cudaGetSymbolAddress(&p, g_att); patt = (float*)p;
        cudaGetSymbolAddress(&p, g_tmp); ptmp = (float*)p;
        cudaGetSymbolAddress(&p, g_h);   ph   = (float*)p;
        cudaGetSymbolAddress(&p, g_rl);  prl  = (float*)p;
    }

    float* out = (float*)d_out;
    const size_t BTV = (size_t)BTc * Vc;

    // 1. Embedding
    embed_kernel<<<BTc, 256>>>(idx, tok_emb, pos_emb, px);

    for (int l = 0; l < Lc; l++) {
        const float* wq = Wq + (size_t)l * Dhc * Dhc;
        const float* wk = Wk + (size_t)l * Dhc * Dhc;
        const float* wv = Wv + (size_t)l * Dhc * Dhc;
        const float* wo = Wo + (size_t)l * Ec * Ec;
        const float* bol = bo + (size_t)l * Ec;
        const float* w1 = W1 + (size_t)l * FFc * Ec;
        const float* b1l = b1 + (size_t)l * FFc;
        const float* w2 = W2 + (size_t)l * Ec * FFc;
        const float* b2l = b2 + (size_t)l * Ec;
        const float* g1 = ln1_g + (size_t)l * Ec;
        const float* be1 = ln1_b + (size_t)l * Ec;
        const float* g2 = ln2_g + (size_t)l * Ec;
        const float* be2 = ln2_b + (size_t)l * Ec;

        // 2. QKV per-head projections: [131072,64] @ [64,64]^T
        dim3 gp(1, ROWSQKV / 128);
        gemm_kernel<<<gp, 256>>>(px, wq, nullptr, nullptr, pq, ROWSQKV, Dhc, Dhc, 0);
        gemm_kernel<<<gp, 256>>>(px, wk, nullptr, nullptr, pk, ROWSQKV, Dhc, Dhc, 0);
        gemm_kernel<<<gp, 256>>>(px, wv, nullptr, nullptr, pv, ROWSQKV, Dhc, Dhc, 0);

        // 3. Causal attention
        attn_kernel<<<dim3(Tc / 8, Bc * Hc), 256>>>(pq, pk, pv, patt);

        // 4. Output projection + bias + residual, then LN1
        gemm_kernel<<<dim3(Ec / 128, BTc / 128), 256>>>(patt, wo, bol, px, ptmp,
                                                        BTc, Ec, Ec, 0);
        layernorm_kernel<<<BTc, 256>>>(ptmp, g1, be1, px);

        // 5. FFN: gelu(x@W1^T+b1) @ W2^T + b2 + residual, then LN2
        gemm_kernel<<<dim3(FFc / 128, BTc / 128), 256>>>(px, w1, b1l, nullptr, ph,
                                                         BTc, FFc, Ec, 1);
        gemm_kernel<<<dim3(Ec / 128, BTc / 128), 256>>>(ph, w2, b2l, px, ptmp,
                                                        BTc, Ec, FFc, 0);
        layernorm_kernel<<<BTc, 256>>>(ptmp, g2, be2, px);
    }

    // 6. Final LN
    layernorm_kernel<<<BTc, 256>>>(px, lnf_g, lnf_b, ptmp);

    // 7. LM head -> logits directly into d_out
    gemm_kernel<<<dim3((Vc + 127) / 128, BTc / 128), 256>>>(ptmp, lm_w, lm_b, nullptr,
                                                            out, BTc, Vc, Ec, 0);

    // 8. Loss
    rowloss_kernel<<<BTc, 256>>>(out, targets, prl);
    if ((size_t)out_size > BTV) {
        loss_reduce_kernel<<<1, 256>>>(prl, out + BTV);
    }
}

// round 6
// speedup vs baseline: 1.6763x; 1.6763x over previous
#include <cuda_runtime.h>
#include <cuda_bf16.h>
#include <math.h>
#include <stdint.h>

// ---------------------------------------------------------------------------
// Problem constants
// ---------------------------------------------------------------------------
#define Vc 32000
#define Ec 1024
#define Tc 2048
#define Hc 16
#define Dhc 64
#define Lc 4
#define FFc 4096
#define Bc 4
#define BTc (Bc * Tc)          // 8192 rows
#define ROWSQKV (Bc * Tc * Hc) // 131072 rows of 64

// ---------------------------------------------------------------------------
// Scratch (device globals; no allocation allowed)
// ---------------------------------------------------------------------------
__device__ float g_x[BTc * Ec];     // activations [B,T,E]
__device__ float g_q[BTc * Ec];
__device__ float g_k[BTc * Ec];
__device__ float g_v[BTc * Ec];
__device__ float g_att[BTc * Ec];   // attention output [B,T,E]
__device__ float g_tmp[BTc * Ec];   // pre-LN residual sums
__device__ float g_h[BTc * FFc];    // FFN hidden
__device__ float g_rl[BTc];         // per-row loss

// ---------------------------------------------------------------------------
// Embedding: x[b,t,:] = tok_emb[idx[b,t],:] + pos_emb[t,:]
// ---------------------------------------------------------------------------
__global__ void embed_kernel(const int* __restrict__ idx,
                             const float* __restrict__ tok,
                             const float* __restrict__ pos,
                             float* __restrict__ x) {
    int bt = blockIdx.x;
    int tid = threadIdx.x;
    int token = idx[bt];
    int t = bt % Tc;
    float4 a = *(const float4*)(tok + (size_t)token * Ec + tid * 4);
    float4 p = *(const float4*)(pos + (size_t)t * Ec + tid * 4);
    float4 r;
    r.x = a.x + p.x; r.y = a.y + p.y; r.z = a.z + p.z; r.w = a.w + p.w;
    *(float4*)(x + (size_t)bt * Ec + tid * 4) = r;
}

// ---------------------------------------------------------------------------
// tf32 helpers
// ---------------------------------------------------------------------------
__device__ __forceinline__ unsigned int f2tf32(float x) {
    unsigned int r;
    asm("cvt.rna.tf32.f32 %0, %1;" : "=r"(r) : "f"(x));
    return r;
}

__device__ __forceinline__ void mma_tf32(float* c, const unsigned int* a,
                                         const unsigned int* b) {
    asm volatile(
        "mma.sync.aligned.m16n8k8.row.col.f32.tf32.tf32.f32 "
        "{%0,%1,%2,%3}, {%4,%5,%6,%7}, {%8,%9}, {%0,%1,%2,%3};"
        : "+f"(c[0]), "+f"(c[1]), "+f"(c[2]), "+f"(c[3])
        : "r"(a[0]), "r"(a[1]), "r"(a[2]), "r"(a[3]), "r"(b[0]), "r"(b[1]));
}

// ---------------------------------------------------------------------------
// TF32 tensor-core GEMM: C[m,n] = sum_k A[m,k]*W[n,k] + bias[n]
// Optional exact GELU, optional residual add. Requires M%128==0, N%128==0,
// K%16==0 (true for all call sites: N in {1024,4096,32000}, K in {1024,4096}).
// Block tile 128x128, BK=16. 8 warps, each 32(m) x 64(n) = 2x8 m16n8k8 tiles.
// Smem ldm=132 => conflict-free fragment loads.
// ---------------------------------------------------------------------------
#define LDMS 132

__global__ __launch_bounds__(256)
void gemm_tf32_kernel(const float* __restrict__ A, const float* __restrict__ W,
                      const float* __restrict__ bias, const float* __restrict__ resid,
                      float* __restrict__ C, int M, int N, int K, int do_gelu) {
    __shared__ unsigned int As[16][LDMS];
    __shared__ unsigned int Bs[16][LDMS];

    const int tid = threadIdx.x;
    const int lane = tid & 31;
    const int warp = tid >> 5;
    const int wm = warp >> 1;       // 0..3 -> m offset wm*32
    const int wn = warp & 1;        // 0..1 -> n offset wn*64
    const int m0 = blockIdx.y * 128;
    const int n0 = blockIdx.x * 128;

    // staging assignment: each thread loads 2 float4 from A and 2 from W
    const int ms = tid >> 2;            // 0..63
    const int kq = (tid & 3) << 2;      // 0,4,8,12
    const float* Ap0 = A + (size_t)(m0 + ms) * K + kq;
    const float* Ap1 = A + (size_t)(m0 + ms + 64) * K + kq;
    const float* Wp0 = W + (size_t)(n0 + ms) * K + kq;
    const float* Wp1 = W + (size_t)(n0 + ms + 64) * K + kq;

    float acc[2][8][4];
#pragma unroll
    for (int mi = 0; mi < 2; mi++)
#pragma unroll
        for (int nj = 0; nj < 8; nj++)
#pragma unroll
            for (int i = 0; i < 4; i++) acc[mi][nj][i] = 0.f;

    // prefetch first tile
    float4 ra0 = *(const float4*)(Ap0);
    float4 ra1 = *(const float4*)(Ap1);
    float4 rb0 = *(const float4*)(Wp0);
    float4 rb1 = *(const float4*)(Wp1);

    for (int k0 = 0; k0 < K; k0 += 16) {
        // store staged regs into smem (tf32-rounded)
        As[kq + 0][ms]      = f2tf32(ra0.x);
        As[kq + 1][ms]      = f2tf32(ra0.y);
        As[kq + 2][ms]      = f2tf32(ra0.z);
        As[kq + 3][ms]      = f2tf32(ra0.w);
        As[kq + 0][ms + 64] = f2tf32(ra1.x);
        As[kq + 1][ms + 64] = f2tf32(ra1.y);
        As[kq + 2][ms + 64] = f2tf32(ra1.z);
        As[kq + 3][ms + 64] = f2tf32(ra1.w);
        Bs[kq + 0][ms]      = f2tf32(rb0.x);
        Bs[kq + 1][ms]      = f2tf32(rb0.y);
        Bs[kq + 2][ms]      = f2tf32(rb0.z);
        Bs[kq + 3][ms]      = f2tf32(rb0.w);
        Bs[kq + 0][ms + 64] = f2tf32(rb1.x);
        Bs[kq + 1][ms + 64] = f2tf32(rb1.y);
        Bs[kq + 2][ms + 64] = f2tf32(rb1.z);
        Bs[kq + 3][ms + 64] = f2tf32(rb1.w);
        __syncthreads();

        // issue next tile's global loads early (overlap with MMA)
        if (k0 + 16 < K) {
            ra0 = *(const float4*)(Ap0 + k0 + 16);
            ra1 = *(const float4*)(Ap1 + k0 + 16);
            rb0 = *(const float4*)(Wp0 + k0 + 16);
            rb1 = *(const float4*)(Wp1 + k0 + 16);
        }

#pragma unroll
        for (int kk = 0; kk < 16; kk += 8) {
            const int ka = kk + (lane & 3);
            const int rowA = wm * 32 + (lane >> 2);
            const int colB = wn * 64 + (lane >> 2);

            unsigned int afr[2][4];
#pragma unroll
            for (int mi = 0; mi < 2; mi++) {
                afr[mi][0] = As[ka][rowA + mi * 16];
                afr[mi][1] = As[ka][rowA + mi * 16 + 8];
                afr[mi][2] = As[ka + 4][rowA + mi * 16];
                afr[mi][3] = As[ka + 4][rowA + mi * 16 + 8];
            }
            unsigned int bfr[8][2];
#pragma unroll
            for (int nj = 0; nj < 8; nj++) {
                bfr[nj][0] = Bs[ka][colB + nj * 8];
                bfr[nj][1] = Bs[ka + 4][colB + nj * 8];
            }
#pragma unroll
            for (int mi = 0; mi < 2; mi++)
#pragma unroll
                for (int nj = 0; nj < 8; nj++)
                    mma_tf32(acc[mi][nj], afr[mi], bfr[nj]);
        }
        __syncthreads();
    }

    // epilogue
#pragma unroll
    for (int mi = 0; mi < 2; mi++) {
        const int row = m0 + wm * 32 + mi * 16 + (lane >> 2);
#pragma unroll
        for (int nj = 0; nj < 8; nj++) {
            const int col = n0 + wn * 64 + nj * 8 + (lane & 3) * 2;
            float v0 = acc[mi][nj][0], v1 = acc[mi][nj][1];
            float v2 = acc[mi][nj][2], v3 = acc[mi][nj][3];
            if (bias) {
                float b0 = bias[col], b1 = bias[col + 1];
                v0 += b0; v1 += b1; v2 += b0; v3 += b1;
            }
            if (do_gelu) {
                v0 = 0.5f * v0 * (1.f + erff(v0 * 0.70710678118654752f));
                v1 = 0.5f * v1 * (1.f + erff(v1 * 0.70710678118654752f));
                v2 = 0.5f * v2 * (1.f + erff(v2 * 0.70710678118654752f));
                v3 = 0.5f * v3 * (1.f + erff(v3 * 0.70710678118654752f));
            }
            if (resid) {
                float2 r0 = *(const float2*)(resid + (size_t)row * N + col);
                float2 r1 = *(const float2*)(resid + (size_t)(row + 8) * N + col);
                v0 += r0.x; v1 += r0.y; v2 += r1.x; v3 += r1.y;
            }
            float2 o0 = make_float2(v0, v1);
            float2 o1 = make_float2(v2, v3);
            *(float2*)(C + (size_t)row * N + col) = o0;
            *(float2*)(C + (size_t)(row + 8) * N + col) = o1;
        }
    }
}

// ---------------------------------------------------------------------------
// Scalar SGEMM (kept for the small per-head QKV projections, N=K=64)
// ---------------------------------------------------------------------------
__global__ __launch_bounds__(256)
void gemm_kernel(const float* __restrict__ A, const float* __restrict__ W,
                 const float* __restrict__ bias, const float* __restrict__ resid,
                 float* __restrict__ C, int M, int N, int K, int do_gelu) {
    __shared__ float As[8][128];
    __shared__ float Ws[8][128];

    int tid = threadIdx.x;
    int tx = tid % 16;
    int ty = tid / 16;
    int m0 = blockIdx.y * 128;
    int n0 = blockIdx.x * 128;

    float acc[8][8];
#pragma unroll
    for (int i = 0; i < 8; i++)
#pragma unroll
        for (int j = 0; j < 8; j++) acc[i][j] = 0.f;

    int arow = tid >> 1;
    int acol = (tid & 1) * 4;
    const float* Aptr = A + (size_t)(m0 + arow) * K + acol;
    bool wvalid = (n0 + arow) < N;
    const float* Wptr = W + (size_t)(n0 + arow) * K + acol;

    for (int k0 = 0; k0 < K; k0 += 8) {
        float4 av = *(const float4*)(Aptr + k0);
        float4 wv = wvalid ? *(const float4*)(Wptr + k0) : make_float4(0.f, 0.f, 0.f, 0.f);
        As[acol + 0][arow] = av.x;
        As[acol + 1][arow] = av.y;
        As[acol + 2][arow] = av.z;
        As[acol + 3][arow] = av.w;
        Ws[acol + 0][arow] = wv.x;
        Ws[acol + 1][arow] = wv.y;
        Ws[acol + 2][arow] = wv.z;
        Ws[acol + 3][arow] = wv.w;
        __syncthreads();

#pragma unroll
        for (int k = 0; k < 8; k++) {
            float4 a0 = *(const float4*)&As[k][ty * 8];
            float4 a1 = *(const float4*)&As[k][ty * 8 + 4];
            float4 b0 = *(const float4*)&Ws[k][tx * 8];
            float4 b1 = *(const float4*)&Ws[k][tx * 8 + 4];
            float ar[8] = {a0.x, a0.y, a0.z, a0.w, a1.x, a1.y, a1.z, a1.w};
            float br[8] = {b0.x, b0.y, b0.z, b0.w, b1.x, b1.y, b1.z, b1.w};
#pragma unroll
            for (int i = 0; i < 8; i++)
#pragma unroll
                for (int j = 0; j < 8; j++) acc[i][j] += ar[i] * br[j];
        }
        __syncthreads();
    }

#pragma unroll
    for (int i = 0; i < 8; i++) {
        int mrow = m0 + ty * 8 + i;
#pragma unroll
        for (int j = 0; j < 8; j++) {
            int ncol = n0 + tx * 8 + j;
            if (ncol < N) {
                float v = acc[i][j];
                if (bias) v += bias[ncol];
                if (do_gelu) v = 0.5f * v * (1.f + erff(v * 0.70710678118654752f));
                if (resid) v += resid[(size_t)mrow * N + ncol];
                C[(size_t)mrow * N + ncol] = v;
            }
        }
    }
}

// ---------------------------------------------------------------------------
// LayerNorm over last dim (E=1024). One block (256 thr) per row.
// ---------------------------------------------------------------------------
__global__ __launch_bounds__(256)
void layernorm_kernel(const float* __restrict__ in, const float* __restrict__ gamma,
                      const float* __restrict__ beta, float* __restrict__ out) {
    __shared__ float red[256];
    int row = blockIdx.x;
    int tid = threadIdx.x;
    const float* x = in + (size_t)row * Ec;
    float4 xv = *(const float4*)(x + tid * 4);

    float s = xv.x + xv.y + xv.z + xv.w;
    red[tid] = s;
    __syncthreads();
#pragma unroll
    for (int st = 128; st; st >>= 1) {
        if (tid < st) red[tid] += red[tid + st];
        __syncthreads();
    }
    float mean = red[0] * (1.f / Ec);
    __syncthreads();

    float d0 = xv.x - mean, d1 = xv.y - mean, d2 = xv.z - mean, d3 = xv.w - mean;
    red[tid] = d0 * d0 + d1 * d1 + d2 * d2 + d3 * d3;
    __syncthreads();
#pragma unroll
    for (int st = 128; st; st >>= 1) {
        if (tid < st) red[tid] += red[tid + st];
        __syncthreads();
    }
    float var = red[0] * (1.f / Ec);
    float r = rsqrtf(var + 1e-5f);

    float4 gv = *(const float4*)(gamma + tid * 4);
    float4 bv = *(const float4*)(beta + tid * 4);
    float4 o;
    o.x = d0 * r * gv.x + bv.x;
    o.y = d1 * r * gv.y + bv.y;
    o.z = d2 * r * gv.z + bv.z;
    o.w = d3 * r * gv.w + bv.w;
    *(float4*)(out + (size_t)row * Ec + tid * 4) = o;
}

// ---------------------------------------------------------------------------
// Causal flash attention (fp32 scalar). Q/K/V/O: [B,T,H,Dh].
// ---------------------------------------------------------------------------
__global__ __launch_bounds__(256)
void attn_kernel(const float* __restrict__ Q, const float* __restrict__ Kb,
                 const float* __restrict__ Vb, float* __restrict__ O) {
    __shared__ float Ks[64][65];
    __shared__ float Vs[64][65];
    __shared__ float qs[8][65];
    __shared__ float ps[8][64];

    int tid = threadIdx.x;
    int w = tid >> 5;
    int lane = tid & 31;
    int qblk = blockIdx.x;
    int bh = blockIdx.y;
    int b = bh / Hc, h = bh % Hc;
    int q = qblk * 8 + w;

    for (int i = tid; i < 8 * 64; i += 256) {
        int qq = i >> 6, d = i & 63;
        qs[qq][d] = Q[(((size_t)b * Tc + qblk * 8 + qq) * Hc + h) * Dhc + d];
    }
    __syncthreads();

    float m = -INFINITY, l = 0.f, o0 = 0.f, o1 = 0.f;
    int d0 = lane, d1 = lane + 32;
    int j0 = lane, j1 = lane + 32;
    int kmax = qblk * 8 + 7;
    int ntiles = (kmax + 64) / 64;

    for (int t = 0; t < ntiles; t++) {
        int k0 = t * 64;
        for (int i = tid; i < 64 * 64; i += 256) {
            int r = i >> 6, c = i & 63;
            size_t gidx = (((size_t)b * Tc + k0 + r) * Hc + h) * Dhc + c;
            Ks[r][c] = Kb[gidx];
            Vs[r][c] = Vb[gidx];
        }
        __syncthreads();

        float s0 = 0.f, s1 = 0.f;
#pragma unroll 16
        for (int d = 0; d < 64; d++) {
            float qd = qs[w][d];
            s0 += qd * Ks[j0][d];
            s1 += qd * Ks[j1][d];
        }
        s0 *= 0.125f;
        s1 *= 0.125f;
        if (k0 + j0 > q) s0 = -INFINITY;
        if (k0 + j1 > q) s1 = -INFINITY;

        float smax = fmaxf(s0, s1);
#pragma unroll
        for (int off = 16; off; off >>= 1)
            smax = fmaxf(smax, __shfl_xor_sync(0xFFFFFFFFu, smax, off));
        float mnew = fmaxf(m, smax);
        float alpha = expf(m - mnew);
        float p0 = expf(s0 - mnew);
        float p1 = expf(s1 - mnew);
        float psum = p0 + p1;
#pragma unroll
        for (int off = 16; off; off >>= 1)
            psum += __shfl_xor_sync(0xFFFFFFFFu, psum, off);
        l = l * alpha + psum;
        o0 *= alpha;
        o1 *= alpha;
        ps[w][j0] = p0;
        ps[w][j1] = p1;
        __syncwarp();
#pragma unroll 16
        for (int j = 0; j < 64; j++) {
            float pj = ps[w][j];
            o0 += pj * Vs[j][d0];
            o1 += pj * Vs[j][d1];
        }
        m = mnew;
        __syncthreads();
    }

    float inv = 1.f / l;
    size_t ob = (((size_t)b * Tc + q) * Hc + h) * Dhc;
    O[ob + d0] = o0 * inv;
    O[ob + d1] = o1 * inv;
}

// ---------------------------------------------------------------------------
// Per-row loss: rl[r] = logsumexp(logits[r,:]) - logits[r, target[r]]
// ---------------------------------------------------------------------------
__global__ __launch_bounds__(256)
void rowloss_kernel(const float* __restrict__ logits, const int* __restrict__ targets,
                    float* __restrict__ rl) {
    __shared__ float red[256];
    int row = blockIdx.x;
    int tid = threadIdx.x;
    const float* lg = logits + (size_t)row * Vc;

    float mx = -INFINITY;
    for (int i = tid; i < Vc; i += 256) mx = fmaxf(mx, lg[i]);
    red[tid] = mx;
    __syncthreads();
#pragma unroll
    for (int st = 128; st; st >>= 1) {
        if (tid < st) red[tid] = fmaxf(red[tid], red[tid + st]);
        __syncthreads();
    }
    mx = red[0];
    __syncthreads();

    float s = 0.f;
    for (int i = tid; i < Vc; i += 256) s += expf(lg[i] - mx);
    red[tid] = s;
    __syncthreads();
#pragma unroll
    for (int st = 128; st; st >>= 1) {
        if (tid < st) red[tid] += red[tid + st];
        __syncthreads();
    }
    if (tid == 0) rl[row] = (mx + logf(red[0])) - lg[targets[row]];
}

__global__ __launch_bounds__(256)
void loss_reduce_kernel(const float* __restrict__ rl, float* __restrict__ out) {
    __shared__ float red[256];
    int tid = threadIdx.x;
    float s = 0.f;
    for (int i = tid; i < BTc; i += 256) s += rl[i];
    red[tid] = s;
    __syncthreads();
#pragma unroll
    for (int st = 128; st; st >>= 1) {
        if (tid < st) red[tid] += red[tid + st];
        __syncthreads();
    }
    if (tid == 0) *out = red[0] / (float)BTc;
}

// ---------------------------------------------------------------------------
// Host orchestration (graph-capturable: kernel launches only)
// ---------------------------------------------------------------------------
extern "C" void kernel_launch(void* const* d_in, const int* in_sizes, int n_in,
                              void* d_out, int out_size) {
    const int*   idx     = (const int*)d_in[0];
    const int*   targets = (const int*)d_in[1];
    const float* tok_emb = (const float*)d_in[2];
    const float* pos_emb = (const float*)d_in[3];
    const float* Wq      = (const float*)d_in[4];
    const float* Wk      = (const float*)d_in[5];
    const float* Wv      = (const float*)d_in[6];
    const float* Wo      = (const float*)d_in[7];
    const float* bo      = (const float*)d_in[8];
    const float* ln1_g   = (const float*)d_in[9];
    const float* ln1_b   = (const float*)d_in[10];
    const float* W1      = (const float*)d_in[11];
    const float* b1      = (const float*)d_in[12];
    const float* W2      = (const float*)d_in[13];
    const float* b2      = (const float*)d_in[14];
    const float* ln2_g   = (const float*)d_in[15];
    const float* ln2_b   = (const float*)d_in[16];
    const float* lnf_g   = (const float*)d_in[17];
    const float* lnf_b   = (const float*)d_in[18];
    const float* lm_w    = (const float*)d_in[19];
    const float* lm_b    = (const float*)d_in[20];

    static float *px = nullptr, *pq, *pk, *pv, *patt, *ptmp, *ph, *prl;
    if (!px) {
        void* p;
        cudaGetSymbolAddress(&p, g_x);   px   = (float*)p;
        cudaGetSymbolAddress(&p, g_q);   pq   = (float*)p;
        cudaGetSymbolAddress(&p, g_k);   pk   = (float*)p;
        cudaGetSymbolAddress(&p, g_v);   pv   = (float*)p;
        cudaGetSymbolAddress(&p, g_att); patt = (float*)p;
        cudaGetSymbolAddress(&p, g_tmp); ptmp = (float*)p;
        cudaGetSymbolAddress(&p, g_h);   ph   = (float*)p;
        cudaGetSymbolAddress(&p, g_rl);  prl  = (float*)p;
    }

    float* out = (float*)d_out;
    const size_t BTV = (size_t)BTc * Vc;

    // 1. Embedding
    embed_kernel<<<BTc, 256>>>(idx, tok_emb, pos_emb, px);

    for (int l = 0; l < Lc; l++) {
        const float* wq = Wq + (size_t)l * Dhc * Dhc;
        const float* wk = Wk + (size_t)l * Dhc * Dhc;
        const float* wv = Wv + (size_t)l * Dhc * Dhc;
        const float* wo = Wo + (size_t)l * Ec * Ec;
        const float* bol = bo + (size_t)l * Ec;
        const float* w1 = W1 + (size_t)l * FFc * Ec;
        const float* b1l = b1 + (size_t)l * FFc;
        const float* w2 = W2 + (size_t)l * Ec * FFc;
        const float* b2l = b2 + (size_t)l * Ec;
        const float* g1 = ln1_g + (size_t)l * Ec;
        const float* be1 = ln1_b + (size_t)l * Ec;
        const float* g2 = ln2_g + (size_t)l * Ec;
        const float* be2 = ln2_b + (size_t)l * Ec;

        // 2. QKV per-head projections: [131072,64] @ [64,64]^T (scalar kernel)
        dim3 gp(1, ROWSQKV / 128);
        gemm_kernel<<<gp, 256>>>(px, wq, nullptr, nullptr, pq, ROWSQKV, Dhc, Dhc, 0);
        gemm_kernel<<<gp, 256>>>(px, wk, nullptr, nullptr, pk, ROWSQKV, Dhc, Dhc, 0);
        gemm_kernel<<<gp, 256>>>(px, wv, nullptr, nullptr, pv, ROWSQKV, Dhc, Dhc, 0);

        // 3. Causal attention
        attn_kernel<<<dim3(Tc / 8, Bc * Hc), 256>>>(pq, pk, pv, patt);

        // 4. Output projection + bias + residual, then LN1  (tf32 MMA)
        gemm_tf32_kernel<<<dim3(Ec / 128, BTc / 128), 256>>>(patt, wo, bol, px, ptmp,
                                                             BTc, Ec, Ec, 0);
        layernorm_kernel<<<BTc, 256>>>(ptmp, g1, be1, px);

        // 5. FFN: gelu(x@W1^T+b1) @ W2^T + b2 + residual, then LN2  (tf32 MMA)
        gemm_tf32_kernel<<<dim3(FFc / 128, BTc / 128), 256>>>(px, w1, b1l, nullptr, ph,
                                                              BTc, FFc, Ec, 1);
        gemm_tf32_kernel<<<dim3(Ec / 128, BTc / 128), 256>>>(ph, w2, b2l, px, ptmp,
                                                             BTc, Ec, FFc, 0);
        layernorm_kernel<<<BTc, 256>>>(ptmp, g2, be2, px);
    }

    // 6. Final LN
    layernorm_kernel<<<BTc, 256>>>(px, lnf_g, lnf_b, ptmp);

    // 7. LM head -> logits directly into d_out  (tf32 MMA; 32000 = 250*128)
    gemm_tf32_kernel<<<dim3(Vc / 128, BTc / 128), 256>>>(ptmp, lm_w, lm_b, nullptr,
                                                         out, BTc, Vc, Ec, 0);

    // 8. Loss
    rowloss_kernel<<<BTc, 256>>>(out, targets, prl);
    if ((size_t)out_size > BTV) {
        loss_reduce_kernel<<<1, 256>>>(prl, out + BTV);
    }
}

// round 10
// speedup vs baseline: 1.9216x; 1.1463x over previous
#include <cuda_runtime.h>
#include <cuda_bf16.h>
#include <math.h>
#include <stdint.h>

// ---------------------------------------------------------------------------
// Problem constants
// ---------------------------------------------------------------------------
#define Vc 32000
#define Ec 1024
#define Tc 2048
#define Hc 16
#define Dhc 64
#define Lc 4
#define FFc 4096
#define Bc 4
#define BTc (Bc * Tc)          // 8192 rows
#define ROWSQKV (Bc * Tc * Hc) // 131072 rows of 64

// ---------------------------------------------------------------------------
// Scratch (device globals; no allocation allowed)
// ---------------------------------------------------------------------------
__device__ float g_x[BTc * Ec];     // activations [B,T,E]
__device__ float g_q[BTc * Ec];
__device__ float g_k[BTc * Ec];
__device__ float g_v[BTc * Ec];
__device__ float g_att[BTc * Ec];   // attention output [B,T,E]
__device__ float g_tmp[BTc * Ec];   // pre-LN residual sums
__device__ float g_h[BTc * FFc];    // FFN hidden
__device__ float g_rl[BTc];         // per-row loss

// ---------------------------------------------------------------------------
// Embedding
// ---------------------------------------------------------------------------
__global__ void embed_kernel(const int* __restrict__ idx,
                             const float* __restrict__ tok,
                             const float* __restrict__ pos,
                             float* __restrict__ x) {
    int bt = blockIdx.x;
    int tid = threadIdx.x;
    int token = idx[bt];
    int t = bt % Tc;
    float4 a = *(const float4*)(tok + (size_t)token * Ec + tid * 4);
    float4 p = *(const float4*)(pos + (size_t)t * Ec + tid * 4);
    float4 r;
    r.x = a.x + p.x; r.y = a.y + p.y; r.z = a.z + p.z; r.w = a.w + p.w;
    *(float4*)(x + (size_t)bt * Ec + tid * 4) = r;
}

// ---------------------------------------------------------------------------
// tf32 helpers
// ---------------------------------------------------------------------------
__device__ __forceinline__ unsigned int f2tf32(float x) {
    unsigned int r;
    asm("cvt.rna.tf32.f32 %0, %1;" : "=r"(r) : "f"(x));
    return r;
}

__device__ __forceinline__ void mma_tf32(float* c, const unsigned int* a,
                                         const unsigned int* b) {
    asm volatile(
        "mma.sync.aligned.m16n8k8.row.col.f32.tf32.tf32.f32 "
        "{%0,%1,%2,%3}, {%4,%5,%6,%7}, {%8,%9}, {%0,%1,%2,%3};"
        : "+f"(c[0]), "+f"(c[1]), "+f"(c[2]), "+f"(c[3])
        : "r"(a[0]), "r"(a[1]), "r"(a[2]), "r"(a[3]), "r"(b[0]), "r"(b[1]));
}

__device__ __forceinline__ void ldsm_x4(unsigned int* r, unsigned int smaddr) {
    asm volatile(
        "ldmatrix.sync.aligned.m8n8.x4.shared.b16 {%0,%1,%2,%3}, [%4];"
        : "=r"(r[0]), "=r"(r[1]), "=r"(r[2]), "=r"(r[3])
        : "r"(smaddr));
}

// ---------------------------------------------------------------------------
// TF32 tensor-core GEMM with ldmatrix fragments + double-buffered smem.
// C[m,n] = sum_k A[m,k]*W[n,k] (+bias, optional GELU, optional residual).
// Requires M%128==0, N%128==0, K%16==0. Block 128x128, BK=16, 2 stages.
// Smem layout: [row][k] with pitch 20 words (80B) -> conflict-free LDSM.
// ---------------------------------------------------------------------------
#define PITCH 20

__global__ __launch_bounds__(256)
void gemm_tf32_kernel(const float* __restrict__ A, const float* __restrict__ W,
                      const float* __restrict__ bias, const float* __restrict__ resid,
                      float* __restrict__ C, int M, int N, int K, int do_gelu) {
    __shared__ __align__(16) unsigned int As[2][128][PITCH];
    __shared__ __align__(16) unsigned int Bs[2][128][PITCH];

    const int tid = threadIdx.x;
    const int lane = tid & 31;
    const int warp = tid >> 5;
    const int wm = warp >> 1;       // 0..3 -> m offset wm*32
    const int wn = warp & 1;        // 0..1 -> n offset wn*64
    const int m0 = blockIdx.y * 128;
    const int n0 = blockIdx.x * 128;

    // staging: each thread converts+stores one float4 into rows ms and ms+64
    const int ms = tid >> 2;            // 0..63
    const int kq = (tid & 3) << 2;      // 0,4,8,12
    const float* Ap0 = A + (size_t)(m0 + ms) * K + kq;
    const float* Ap1 = A + (size_t)(m0 + ms + 64) * K + kq;
    const float* Wp0 = W + (size_t)(n0 + ms) * K + kq;
    const float* Wp1 = W + (size_t)(n0 + ms + 64) * K + kq;

    // ldmatrix lane address components
    const int arow = wm * 32 + (lane & 7) + ((lane >> 3) & 1) * 8;  // + mi*16
    const int akw = ((lane >> 4) & 1) * 4;                          // + kk
    const int brow = wn * 64 + (lane & 7) + ((lane >> 4) & 1) * 8;  // + nj2*16
    const int bkw = ((lane >> 3) & 1) * 4;                          // + kk

    const unsigned int sA = (unsigned int)__cvta_generic_to_shared(&As[0][0][0]);
    const unsigned int sB = (unsigned int)__cvta_generic_to_shared(&Bs[0][0][0]);

    float acc[2][8][4];
#pragma unroll
    for (int mi = 0; mi < 2; mi++)
#pragma unroll
        for (int nj = 0; nj < 8; nj++)
#pragma unroll
            for (int i = 0; i < 4; i++) acc[mi][nj][i] = 0.f;

    // prologue: load + stage tile 0
    float4 ra0 = *(const float4*)(Ap0);
    float4 ra1 = *(const float4*)(Ap1);
    float4 rb0 = *(const float4*)(Wp0);
    float4 rb1 = *(const float4*)(Wp1);
    {
        uint4 t;
        t.x = f2tf32(ra0.x); t.y = f2tf32(ra0.y); t.z = f2tf32(ra0.z); t.w = f2tf32(ra0.w);
        *(uint4*)&As[0][ms][kq] = t;
        t.x = f2tf32(ra1.x); t.y = f2tf32(ra1.y); t.z = f2tf32(ra1.z); t.w = f2tf32(ra1.w);
        *(uint4*)&As[0][ms + 64][kq] = t;
        t.x = f2tf32(rb0.x); t.y = f2tf32(rb0.y); t.z = f2tf32(rb0.z); t.w = f2tf32(rb0.w);
        *(uint4*)&Bs[0][ms][kq] = t;
        t.x = f2tf32(rb1.x); t.y = f2tf32(rb1.y); t.z = f2tf32(rb1.z); t.w = f2tf32(rb1.w);
        *(uint4*)&Bs[0][ms + 64][kq] = t;
    }
    __syncthreads();

    int s = 0;
    for (int k0 = 0; k0 < K; k0 += 16) {
        const bool has_next = (k0 + 16) < K;
        if (has_next) {
            ra0 = *(const float4*)(Ap0 + k0 + 16);
            ra1 = *(const float4*)(Ap1 + k0 + 16);
            rb0 = *(const float4*)(Wp0 + k0 + 16);
            rb1 = *(const float4*)(Wp1 + k0 + 16);
        }

        const unsigned int stA = sA + (unsigned int)(s * 128 * PITCH * 4);
        const unsigned int stB = sB + (unsigned int)(s * 128 * PITCH * 4);

#pragma unroll
        for (int kk = 0; kk < 16; kk += 8) {
            unsigned int afr[2][4];
#pragma unroll
            for (int mi = 0; mi < 2; mi++) {
                unsigned int addr = stA +
                    (unsigned int)(((arow + mi * 16) * PITCH + kk + akw) * 4);
                ldsm_x4(afr[mi], addr);
            }
            unsigned int bfr[4][4];   // [nj2] -> {b0(e), b1(e), b0(o), b1(o)}
#pragma unroll
            for (int nj2 = 0; nj2 < 4; nj2++) {
                unsigned int addr = stB +
                    (unsigned int)(((brow + nj2 * 16) * PITCH + kk + bkw) * 4);
                ldsm_x4(bfr[nj2], addr);
            }
#pragma unroll
            for (int mi = 0; mi < 2; mi++)
#pragma unroll
                for (int nj = 0; nj < 8; nj++)
                    mma_tf32(acc[mi][nj], afr[mi], &bfr[nj >> 1][(nj & 1) * 2]);
        }

        if (has_next) {
            const int ns = s ^ 1;
            uint4 t;
            t.x = f2tf32(ra0.x); t.y = f2tf32(ra0.y); t.z = f2tf32(ra0.z); t.w = f2tf32(ra0.w);
            *(uint4*)&As[ns][ms][kq] = t;
            t.x = f2tf32(ra1.x); t.y = f2tf32(ra1.y); t.z = f2tf32(ra1.z); t.w = f2tf32(ra1.w);
            *(uint4*)&As[ns][ms + 64][kq] = t;
            t.x = f2tf32(rb0.x); t.y = f2tf32(rb0.y); t.z = f2tf32(rb0.z); t.w = f2tf32(rb0.w);
            *(uint4*)&Bs[ns][ms][kq] = t;
            t.x = f2tf32(rb1.x); t.y = f2tf32(rb1.y); t.z = f2tf32(rb1.z); t.w = f2tf32(rb1.w);
            *(uint4*)&Bs[ns][ms + 64][kq] = t;
            __syncthreads();
            s = ns;
        }
    }

    // epilogue (standard mma fragment layout)
#pragma unroll
    for (int mi = 0; mi < 2; mi++) {
        const int row = m0 + wm * 32 + mi * 16 + (lane >> 2);
#pragma unroll
        for (int nj = 0; nj < 8; nj++) {
            const int col = n0 + wn * 64 + nj * 8 + (lane & 3) * 2;
            float v0 = acc[mi][nj][0], v1 = acc[mi][nj][1];
            float v2 = acc[mi][nj][2], v3 = acc[mi][nj][3];
            if (bias) {
                float b0v = bias[col], b1v = bias[col + 1];
                v0 += b0v; v1 += b1v; v2 += b0v; v3 += b1v;
            }
            if (do_gelu) {
                v0 = 0.5f * v0 * (1.f + erff(v0 * 0.70710678118654752f));
                v1 = 0.5f * v1 * (1.f + erff(v1 * 0.70710678118654752f));
                v2 = 0.5f * v2 * (1.f + erff(v2 * 0.70710678118654752f));
                v3 = 0.5f * v3 * (1.f + erff(v3 * 0.70710678118654752f));
            }
            if (resid) {
                float2 r0 = *(const float2*)(resid + (size_t)row * N + col);
                float2 r1 = *(const float2*)(resid + (size_t)(row + 8) * N + col);
                v0 += r0.x; v1 += r0.y; v2 += r1.x; v3 += r1.y;
            }
            *(float2*)(C + (size_t)row * N + col) = make_float2(v0, v1);
            *(float2*)(C + (size_t)(row + 8) * N + col) = make_float2(v2, v3);
        }
    }
}

// ---------------------------------------------------------------------------
// Scalar SGEMM (kept for the small per-head QKV projections, N=K=64)
// ---------------------------------------------------------------------------
__global__ __launch_bounds__(256)
void gemm_kernel(const float* __restrict__ A, const float* __restrict__ W,
                 const float* __restrict__ bias, const float* __restrict__ resid,
                 float* __restrict__ C, int M, int N, int K, int do_gelu) {
    __shared__ float As[8][128];
    __shared__ float Ws[8][128];

    int tid = threadIdx.x;
    int tx = tid % 16;
    int ty = tid / 16;
    int m0 = blockIdx.y * 128;
    int n0 = blockIdx.x * 128;

    float acc[8][8];
#pragma unroll
    for (int i = 0; i < 8; i++)
#pragma unroll
        for (int j = 0; j < 8; j++) acc[i][j] = 0.f;

    int arow = tid >> 1;
    int acol = (tid & 1) * 4;
    const float* Aptr = A + (size_t)(m0 + arow) * K + acol;
    bool wvalid = (n0 + arow) < N;
    const float* Wptr = W + (size_t)(n0 + arow) * K + acol;

    for (int k0 = 0; k0 < K; k0 += 8) {
        float4 av = *(const float4*)(Aptr + k0);
        float4 wv = wvalid ? *(const float4*)(Wptr + k0) : make_float4(0.f, 0.f, 0.f, 0.f);
        As[acol + 0][arow] = av.x;
        As[acol + 1][arow] = av.y;
        As[acol + 2][arow] = av.z;
        As[acol + 3][arow] = av.w;
        Ws[acol + 0][arow] = wv.x;
        Ws[acol + 1][arow] = wv.y;
        Ws[acol + 2][arow] = wv.z;
        Ws[acol + 3][arow] = wv.w;
        __syncthreads();

#pragma unroll
        for (int k = 0; k < 8; k++) {
            float4 a0 = *(const float4*)&As[k][ty * 8];
            float4 a1 = *(const float4*)&As[k][ty * 8 + 4];
            float4 b0 = *(const float4*)&Ws[k][tx * 8];
            float4 b1 = *(const float4*)&Ws[k][tx * 8 + 4];
            float ar[8] = {a0.x, a0.y, a0.z, a0.w, a1.x, a1.y, a1.z, a1.w};
            float br[8] = {b0.x, b0.y, b0.z, b0.w, b1.x, b1.y, b1.z, b1.w};
#pragma unroll
            for (int i = 0; i < 8; i++)
#pragma unroll
                for (int j = 0; j < 8; j++) acc[i][j] += ar[i] * br[j];
        }
        __syncthreads();
    }

#pragma unroll
    for (int i = 0; i < 8; i++) {
        int mrow = m0 + ty * 8 + i;
#pragma unroll
        for (int j = 0; j < 8; j++) {
            int ncol = n0 + tx * 8 + j;
            if (ncol < N) {
                float v = acc[i][j];
                if (bias) v += bias[ncol];
                if (do_gelu) v = 0.5f * v * (1.f + erff(v * 0.70710678118654752f));
                if (resid) v += resid[(size_t)mrow * N + ncol];
                C[(size_t)mrow * N + ncol] = v;
            }
        }
    }
}

// ---------------------------------------------------------------------------
// LayerNorm over last dim (E=1024). One block (256 thr) per row.
// ---------------------------------------------------------------------------
__global__ __launch_bounds__(256)
void layernorm_kernel(const float* __restrict__ in, const float* __restrict__ gamma,
                      const float* __restrict__ beta, float* __restrict__ out) {
    __shared__ float red[256];
    int row = blockIdx.x;
    int tid = threadIdx.x;
    const float* x = in + (size_t)row * Ec;
    float4 xv = *(const float4*)(x + tid * 4);

    float s = xv.x + xv.y + xv.z + xv.w;
    red[tid] = s;
    __syncthreads();
#pragma unroll
    for (int st = 128; st; st >>= 1) {
        if (tid < st) red[tid] += red[tid + st];
        __syncthreads();
    }
    float mean = red[0] * (1.f / Ec);
    __syncthreads();

    float d0 = xv.x - mean, d1 = xv.y - mean, d2 = xv.z - mean, d3 = xv.w - mean;
    red[tid] = d0 * d0 + d1 * d1 + d2 * d2 + d3 * d3;
    __syncthreads();
#pragma unroll
    for (int st = 128; st; st >>= 1) {
        if (tid < st) red[tid] += red[tid + st];
        __syncthreads();
    }
    float var = red[0] * (1.f / Ec);
    float r = rsqrtf(var + 1e-5f);

    float4 gv = *(const float4*)(gamma + tid * 4);
    float4 bv = *(const float4*)(beta + tid * 4);
    float4 o;
    o.x = d0 * r * gv.x + bv.x;
    o.y = d1 * r * gv.y + bv.y;
    o.z = d2 * r * gv.z + bv.z;
    o.w = d3 * r * gv.w + bv.w;
    *(float4*)(out + (size_t)row * Ec + tid * 4) = o;
}

// ---------------------------------------------------------------------------
// Causal flash attention (fp32 scalar). Q/K/V/O: [B,T,H,Dh].
// ---------------------------------------------------------------------------
__global__ __launch_bounds__(256)
void attn_kernel(const float* __restrict__ Q, const float* __restrict__ Kb,
                 const float* __restrict__ Vb, float* __restrict__ O) {
    __shared__ float Ks[64][65];
    __shared__ float Vs[64][65];
    __shared__ float qs[8][65];
    __shared__ float ps[8][64];

    int tid = threadIdx.x;
    int w = tid >> 5;
    int lane = tid & 31;
    int qblk = blockIdx.x;
    int bh = blockIdx.y;
    int b = bh / Hc, h = bh % Hc;
    int q = qblk * 8 + w;

    for (int i = tid; i < 8 * 64; i += 256) {
        int qq = i >> 6, d = i & 63;
        qs[qq][d] = Q[(((size_t)b * Tc + qblk * 8 + qq) * Hc + h) * Dhc + d];
    }
    __syncthreads();

    float m = -INFINITY, l = 0.f, o0 = 0.f, o1 = 0.f;
    int d0 = lane, d1 = lane + 32;
    int j0 = lane, j1 = lane + 32;
    int kmax = qblk * 8 + 7;
    int ntiles = (kmax + 64) / 64;

    for (int t = 0; t < ntiles; t++) {
        int k0 = t * 64;
        for (int i = tid; i < 64 * 64; i += 256) {
            int r = i >> 6, c = i & 63;
            size_t gidx = (((size_t)b * Tc + k0 + r) * Hc + h) * Dhc + c;
            Ks[r][c] = Kb[gidx];
            Vs[r][c] = Vb[gidx];
        }
        __syncthreads();

        float s0 = 0.f, s1 = 0.f;
#pragma unroll 16
        for (int d = 0; d < 64; d++) {
            float qd = qs[w][d];
            s0 += qd * Ks[j0][d];
            s1 += qd * Ks[j1][d];
        }
        s0 *= 0.125f;
        s1 *= 0.125f;
        if (k0 + j0 > q) s0 = -INFINITY;
        if (k0 + j1 > q) s1 = -INFINITY;

        float smax = fmaxf(s0, s1);
#pragma unroll
        for (int off = 16; off; off >>= 1)
            smax = fmaxf(smax, __shfl_xor_sync(0xFFFFFFFFu, smax, off));
        float mnew = fmaxf(m, smax);
        float alpha = expf(m - mnew);
        float p0 = expf(s0 - mnew);
        float p1 = expf(s1 - mnew);
        float psum = p0 + p1;
#pragma unroll
        for (int off = 16; off; off >>= 1)
            psum += __shfl_xor_sync(0xFFFFFFFFu, psum, off);
        l = l * alpha + psum;
        o0 *= alpha;
        o1 *= alpha;
        ps[w][j0] = p0;
        ps[w][j1] = p1;
        __syncwarp();
#pragma unroll 16
        for (int j = 0; j < 64; j++) {
            float pj = ps[w][j];
            o0 += pj * Vs[j][d0];
            o1 += pj * Vs[j][d1];
        }
        m = mnew;
        __syncthreads();
    }

    float inv = 1.f / l;
    size_t ob = (((size_t)b * Tc + q) * Hc + h) * Dhc;
    O[ob + d0] = o0 * inv;
    O[ob + d1] = o1 * inv;
}

// ---------------------------------------------------------------------------
// Per-row loss: rl[r] = logsumexp(logits[r,:]) - logits[r, target[r]]
// ---------------------------------------------------------------------------
__global__ __launch_bounds__(256)
void rowloss_kernel(const float* __restrict__ logits, const int* __restrict__ targets,
                    float* __restrict__ rl) {
    __shared__ float red[256];
    int row = blockIdx.x;
    int tid = threadIdx.x;
    const float* lg = logits + (size_t)row * Vc;

    float mx = -INFINITY;
    for (int i = tid; i < Vc; i += 256) mx = fmaxf(mx, lg[i]);
    red[tid] = mx;
    __syncthreads();
#pragma unroll
    for (int st = 128; st; st >>= 1) {
        if (tid < st) red[tid] = fmaxf(red[tid], red[tid + st]);
        __syncthreads();
    }
    mx = red[0];
    __syncthreads();

    float s = 0.f;
    for (int i = tid; i < Vc; i += 256) s += expf(lg[i] - mx);
    red[tid] = s;
    __syncthreads();
#pragma unroll
    for (int st = 128; st; st >>= 1) {
        if (tid < st) red[tid] += red[tid + st];
        __syncthreads();
    }
    if (tid == 0) rl[row] = (mx + logf(red[0])) - lg[targets[row]];
}

__global__ __launch_bounds__(256)
void loss_reduce_kernel(const float* __restrict__ rl, float* __restrict__ out) {
    __shared__ float red[256];
    int tid = threadIdx.x;
    float s = 0.f;
    for (int i = tid; i < BTc; i += 256) s += rl[i];
    red[tid] = s;
    __syncthreads();
#pragma unroll
    for (int st = 128; st; st >>= 1) {
        if (tid < st) red[tid] += red[tid + st];
        __syncthreads();
    }
    if (tid == 0) *out = red[0] / (float)BTc;
}

// ---------------------------------------------------------------------------
// Host orchestration (graph-capturable: kernel launches only)
// ---------------------------------------------------------------------------
extern "C" void kernel_launch(void* const* d_in, const int* in_sizes, int n_in,
                              void* d_out, int out_size) {
    const int*   idx     = (const int*)d_in[0];
    const int*   targets = (const int*)d_in[1];
    const float* tok_emb = (const float*)d_in[2];
    const float* pos_emb = (const float*)d_in[3];
    const float* Wq      = (const float*)d_in[4];
    const float* Wk      = (const float*)d_in[5];
    const float* Wv      = (const float*)d_in[6];
    const float* Wo      = (const float*)d_in[7];
    const float* bo      = (const float*)d_in[8];
    const float* ln1_g   = (const float*)d_in[9];
    const float* ln1_b   = (const float*)d_in[10];
    const float* W1      = (const float*)d_in[11];
    const float* b1      = (const float*)d_in[12];
    const float* W2      = (const float*)d_in[13];
    const float* b2      = (const float*)d_in[14];
    const float* ln2_g   = (const float*)d_in[15];
    const float* ln2_b   = (const float*)d_in[16];
    const float* lnf_g   = (const float*)d_in[17];
    const float* lnf_b   = (const float*)d_in[18];
    const float* lm_w    = (const float*)d_in[19];
    const float* lm_b    = (const float*)d_in[20];

    static float *px = nullptr, *pq, *pk, *pv, *patt, *ptmp, *ph, *prl;
    if (!px) {
        void* p;
        cudaGetSymbolAddress(&p, g_x);   px   = (float*)p;
        cudaGetSymbolAddress(&p, g_q);   pq   = (float*)p;
        cudaGetSymbolAddress(&p, g_k);   pk   = (float*)p;
        cudaGetSymbolAddress(&p, g_v);   pv   = (float*)p;
        cudaGetSymbolAddress(&p, g_att); patt = (float*)p;
        cudaGetSymbolAddress(&p, g_tmp); ptmp = (float*)p;
        cudaGetSymbolAddress(&p, g_h);   ph   = (float*)p;
        cudaGetSymbolAddress(&p, g_rl);  prl  = (float*)p;
    }

    float* out = (float*)d_out;
    const size_t BTV = (size_t)BTc * Vc;

    // 1. Embedding
    embed_kernel<<<BTc, 256>>>(idx, tok_emb, pos_emb, px);

    for (int l = 0; l < Lc; l++) {
        const float* wq = Wq + (size_t)l * Dhc * Dhc;
        const float* wk = Wk + (size_t)l * Dhc * Dhc;
        const float* wv = Wv + (size_t)l * Dhc * Dhc;
        const float* wo = Wo + (size_t)l * Ec * Ec;
        const float* bol = bo + (size_t)l * Ec;
        const float* w1 = W1 + (size_t)l * FFc * Ec;
        const float* b1l = b1 + (size_t)l * FFc;
        const float* w2 = W2 + (size_t)l * Ec * FFc;
        const float* b2l = b2 + (size_t)l * Ec;
        const float* g1 = ln1_g + (size_t)l * Ec;
        const float* be1 = ln1_b + (size_t)l * Ec;
        const float* g2 = ln2_g + (size_t)l * Ec;
        const float* be2 = ln2_b + (size_t)l * Ec;

        // 2. QKV per-head projections: [131072,64] @ [64,64]^T (scalar kernel)
        dim3 gp(1, ROWSQKV / 128);
        gemm_kernel<<<gp, 256>>>(px, wq, nullptr, nullptr, pq, ROWSQKV, Dhc, Dhc, 0);
        gemm_kernel<<<gp, 256>>>(px, wk, nullptr, nullptr, pk, ROWSQKV, Dhc, Dhc, 0);
        gemm_kernel<<<gp, 256>>>(px, wv, nullptr, nullptr, pv, ROWSQKV, Dhc, Dhc, 0);

        // 3. Causal attention
        attn_kernel<<<dim3(Tc / 8, Bc * Hc), 256>>>(pq, pk, pv, patt);

        // 4. Output projection + bias + residual, then LN1  (tf32 MMA)
        gemm_tf32_kernel<<<dim3(Ec / 128, BTc / 128), 256>>>(patt, wo, bol, px, ptmp,
                                                             BTc, Ec, Ec, 0);
        layernorm_kernel<<<BTc, 256>>>(ptmp, g1, be1, px);

        // 5. FFN: gelu(x@W1^T+b1) @ W2^T + b2 + residual, then LN2  (tf32 MMA)
        gemm_tf32_kernel<<<dim3(FFc / 128, BTc / 128), 256>>>(px, w1, b1l, nullptr, ph,
                                                              BTc, FFc, Ec, 1);
        gemm_tf32_kernel<<<dim3(Ec / 128, BTc / 128), 256>>>(ph, w2, b2l, px, ptmp,
                                                             BTc, Ec, FFc, 0);
        layernorm_kernel<<<BTc, 256>>>(ptmp, g2, be2, px);
    }

    // 6. Final LN
    layernorm_kernel<<<BTc, 256>>>(px, lnf_g, lnf_b, ptmp);

    // 7. LM head -> logits directly into d_out  (tf32 MMA; 32000 = 250*128)
    gemm_tf32_kernel<<<dim3(Vc / 128, BTc / 128), 256>>>(ptmp, lm_w, lm_b, nullptr,
                                                         out, BTc, Vc, Ec, 0);

    // 8. Loss
    rowloss_kernel<<<BTc, 256>>>(out, targets, prl);
    if ((size_t)out_size > BTV) {
        loss_reduce_kernel<<<1, 256>>>(prl, out + BTV);
    }
}